// round 8
// baseline (speedup 1.0000x reference)
#include <cuda_runtime.h>
#include <cuda_bf16.h>
#include <cstdint>
#include <cstddef>

// ---------------- problem constants ----------------
#define BATCH   4096
#define UNITS   1024
#define TSTEPS  128
#define BM      128            // batch rows per tile
#define BN      64             // z-cols per tile = 16 units * 4 gates
#define KC      32             // K elements per chunk (64B rows)
#define NKC     32             // chunks over K=1024
#define ROWB    80             // padded smem row: 64B data + 16B pad (conflict-free ldsm)
#define PL_A    (128 * ROWB)   // 10240 B (Ah/Al: 128 rows)
#define PL_B    (64 * ROWB)    // 5120 B  (Bh/Bl: 64 rows)
#define O_AH    0
#define O_AL    (PL_A)
#define O_BH    (2 * PL_A)
#define O_BL    (2 * PL_A + PL_B)
#define STAGE   (2 * PL_A + 2 * PL_B)   // 30720 B
#define NSTG    3
#define SMEM_DYN (NSTG * STAGE)         // 92160 B (2 CTAs/SM fit)
#define HN      (4096UL * 1024UL)

// ---------------- device-global state ----------------
__device__ __nv_bfloat16 g_hh[2][HN];   // hidden hi (ping/pong)  [4096][1024]
__device__ __nv_bfloat16 g_hl[2][HN];   // hidden lo
__device__ __nv_bfloat16 g_Wh[HN * 4];  // permuted W hi: [n=4u+g][k]  (4096x1024)
__device__ __nv_bfloat16 g_Wl[HN * 4];  // permuted W lo
__device__ float         g_c[HN];       // cell state fp32, in place
__device__ float         g_kp[4 * UNITS];   // permuted input kernel
__device__ float         g_bp[4 * UNITS];   // permuted bias
__device__ float         g_x[BATCH];        // autoregressive feedback input

// ---------------- small helpers ----------------
__device__ __forceinline__ uint32_t smem_u32(const void* p) {
    uint32_t a;
    asm("{ .reg .u64 t; cvta.to.shared.u64 t, %1; cvt.u32.u64 %0, t; }" : "=r"(a) : "l"(p));
    return a;
}
__device__ __forceinline__ void cp16(uint32_t dst, const void* src) {
    asm volatile("cp.async.cg.shared.global [%0], [%1], 16;" :: "r"(dst), "l"(src) : "memory");
}
__device__ __forceinline__ void cp_commit() {
    asm volatile("cp.async.commit_group;" ::: "memory");
}
template <int N>
__device__ __forceinline__ void cp_wait() {
    asm volatile("cp.async.wait_group %0;" :: "n"(N) : "memory");
}
__device__ __forceinline__ void ldsm_x4(uint32_t addr, uint32_t* r) {
    asm volatile("ldmatrix.sync.aligned.m8n8.x4.shared.b16 {%0,%1,%2,%3}, [%4];"
                 : "=r"(r[0]), "=r"(r[1]), "=r"(r[2]), "=r"(r[3]) : "r"(addr));
}
__device__ __forceinline__ void mma_bf16(float* d, const uint32_t* a, const uint32_t* b) {
    asm volatile(
        "mma.sync.aligned.m16n8k16.row.col.f32.bf16.bf16.f32 "
        "{%0,%1,%2,%3}, {%4,%5,%6,%7}, {%8,%9}, {%0,%1,%2,%3};"
        : "+f"(d[0]), "+f"(d[1]), "+f"(d[2]), "+f"(d[3])
        : "r"(a[0]), "r"(a[1]), "r"(a[2]), "r"(a[3]), "r"(b[0]), "r"(b[1]));
}
__device__ __forceinline__ float sigf(float x) {
    return __fdividef(1.0f, 1.0f + __expf(-x));
}
__device__ __forceinline__ float tanhf_(float x) {
    return __fdividef(2.0f, 1.0f + __expf(-2.0f * x)) - 1.0f;
}

// ---------------- prep kernels ----------------
__global__ void prep_w_kernel(const float* __restrict__ W) {
    int u = blockIdx.x * 32 + threadIdx.x;
    int k = blockIdx.y * 8 + threadIdx.y;
    int g = blockIdx.z;
    float v = W[(size_t)k * 4096 + g * 1024 + u];
    __nv_bfloat16 hi = __float2bfloat16(v);
    float lo = v - __bfloat162float(hi);
    size_t o = ((size_t)(4 * u + g)) * 1024 + k;
    g_Wh[o] = hi;
    g_Wl[o] = __float2bfloat16(lo);
}

__global__ void prep_small_kernel(const float* __restrict__ kern, const float* __restrict__ bias) {
    int idx = blockIdx.x * 256 + threadIdx.x;   // 0..4095
    int g = idx & 3, u = idx >> 2;
    int c = g * 1024 + u;
    g_kp[idx] = kern[c];
    g_bp[idx] = bias[c];
    g_x[idx] = 0.0f;
}

__global__ void init_hc_kernel(const float* __restrict__ feat) {
    size_t idx = (size_t)blockIdx.x * 1024 + threadIdx.x;
    int b = blockIdx.x, u = threadIdx.x;
    float v = feat[(size_t)b * 512 + (u & 511)];
    __nv_bfloat16 hi = __float2bfloat16(v);
    float lo = v - __bfloat162float(hi);
    g_hh[0][idx] = hi;
    g_hl[0][idx] = __float2bfloat16(lo);
    g_c[idx] = v;
}

// pred[b] = (h_hi+h_lo)[b,:] . dw + db ; write out[b][t], feedback g_x[b]
__global__ void collect_kernel(const float* __restrict__ dw, const float* __restrict__ db,
                               float* __restrict__ out, int dst, int t) {
    int wid = threadIdx.x >> 5, lid = threadIdx.x & 31;
    int row = blockIdx.x * 8 + wid;
    const __nv_bfloat16* hh = g_hh[dst];
    const __nv_bfloat16* hl = g_hl[dst];
    size_t base = (size_t)row * 1024;
    float s = 0.0f;
    #pragma unroll
    for (int i = 0; i < 32; i++) {
        int u = i * 32 + lid;
        float h = __bfloat162float(hh[base + u]) + __bfloat162float(hl[base + u]);
        s += h * dw[u];
    }
    #pragma unroll
    for (int o = 16; o; o >>= 1) s += __shfl_down_sync(0xFFFFFFFFu, s, o);
    if (lid == 0) {
        float p = s + db[0];
        out[(size_t)row * TSTEPS + t] = p;
        g_x[row] = p;
    }
}

// ---------------- fused LSTM step (bf16 3-pass, 128x64 tiles, 2 CTAs/SM) ----------------
__global__ void __launch_bounds__(256, 2)
step_kernel(int src) {
    extern __shared__ char sm[];
    const int tid = threadIdx.x;
    const int w = tid >> 5, l = tid & 31;
    const int dst = src ^ 1;
    const int mt = blockIdx.x & 31, nt = blockIdx.x >> 5;
    const int m0 = mt << 7;      // batch row base
    const int n0 = nt << 6;      // z col base (64 cols)
    const int u0 = nt << 4;      // unit base (16 units)

    const uint32_t sb = smem_u32(sm);

    // per-plane global row bases for this tile (row stride 2048 B)
    const char* baseA[2] = {
        (const char*)(g_hh[src] + (size_t)m0 * 1024),
        (const char*)(g_hl[src] + (size_t)m0 * 1024)
    };
    const char* baseB[2] = {
        (const char*)(g_Wh + (size_t)n0 * 1024),
        (const char*)(g_Wl + (size_t)n0 * 1024)
    };

    // warp tiling: 4 (m) x 2 (n); warp tile 32x32
    const int m_off = (w & 3) * 32;
    const int n_off = (w >> 2) * 32;

    float acc[2][4][4];
    #pragma unroll
    for (int im = 0; im < 2; im++)
        #pragma unroll
        for (int jn = 0; jn < 4; jn++)
            #pragma unroll
            for (int q = 0; q < 4; q++) acc[im][jn][q] = 0.0f;

    // -------- producer: 1536 x 16B per chunk, 6/thread --------
    auto load_chunk = [&](int kc) {
        const uint32_t so = sb + (uint32_t)(kc % 3) * STAGE;
        const int k0b = kc * KC * 2;   // byte offset along K
        #pragma unroll
        for (int i = 0; i < 6; i++) {
            int o = tid + i * 256;       // 0..1535
            if (o < 1024) {              // A hi/lo: 512 each
                int pl = o >> 9;
                int idx = o & 511;
                int row = idx >> 2, seg = idx & 3;
                uint32_t d = so + (pl ? O_AL : O_AH) + row * ROWB + seg * 16;
                cp16(d, baseA[pl] + (size_t)row * 2048 + k0b + seg * 16);
            } else {                     // B hi/lo: 256 each
                int oo = o - 1024;
                int pl = oo >> 8;
                int idx = oo & 255;
                int row = idx >> 2, seg = idx & 3;
                uint32_t d = so + (pl ? O_BL : O_BH) + row * ROWB + seg * 16;
                cp16(d, baseB[pl] + (size_t)row * 2048 + k0b + seg * 16);
            }
        }
        cp_commit();
    };

    // ldmatrix address helpers (80B rows -> conflict-free)
    auto a_addr = [&](uint32_t base, int im, int ks) -> uint32_t {
        int row = m_off + im * 16 + (l & 15);
        int byte = ks * 32 + ((l >> 4) * 16);
        return base + row * ROWB + byte;
    };
    auto b_addr = [&](uint32_t base, int ks) -> uint32_t {
        int row = n_off + (l & 7) + ((l >> 4) << 3);
        int byte = ks * 32 + (((l >> 3) & 1) * 16);
        return base + row * ROWB + byte;
    };

    // -------- 3-stage pipeline, ONE sync per chunk --------
    load_chunk(0);
    load_chunk(1);
    for (int kc = 0; kc < NKC; kc++) {
        if (kc + 1 < NKC) { cp_wait<1>(); } else { cp_wait<0>(); }
        __syncthreads();
        const uint32_t so = sb + (uint32_t)(kc % 3) * STAGE;
        #pragma unroll
        for (int ks = 0; ks < 2; ks++) {
            uint32_t ah[2][4], al[2][4], bb[8];
            #pragma unroll
            for (int im = 0; im < 2; im++) ldsm_x4(a_addr(so + O_AH, im, ks), ah[im]);
            #pragma unroll
            for (int im = 0; im < 2; im++) ldsm_x4(a_addr(so + O_AL, im, ks), al[im]);
            // B_hi covers n 0..31 of warp tile (2 ldsm_x4 along n? one x4 covers 16 cols x k16;
            // two x4 loads -> 32 cols)
            ldsm_x4(b_addr(so + O_BH, ks), &bb[0]);
            ldsm_x4(b_addr(so + O_BH, ks) + 16 * ROWB, &bb[4]);
            #pragma unroll
            for (int im = 0; im < 2; im++)
                #pragma unroll
                for (int jn = 0; jn < 4; jn++)
                    mma_bf16(acc[im][jn], ah[im], &bb[(jn >> 1) * 4 + (jn & 1) * 2]);
            #pragma unroll
            for (int im = 0; im < 2; im++)
                #pragma unroll
                for (int jn = 0; jn < 4; jn++)
                    mma_bf16(acc[im][jn], al[im], &bb[(jn >> 1) * 4 + (jn & 1) * 2]);
            // B_lo (reuse bb)
            ldsm_x4(b_addr(so + O_BL, ks), &bb[0]);
            ldsm_x4(b_addr(so + O_BL, ks) + 16 * ROWB, &bb[4]);
            #pragma unroll
            for (int im = 0; im < 2; im++)
                #pragma unroll
                for (int jn = 0; jn < 4; jn++)
                    mma_bf16(acc[im][jn], ah[im], &bb[(jn >> 1) * 4 + (jn & 1) * 2]);
        }
        if (kc + 2 < NKC) load_chunk(kc + 2);
    }

    // -------- fragment-direct epilogue (no smem, shfl-paired gates) --------
    // lane pair (l, l^1) owns the 4 gates of one (row, unit):
    //   even lane (l&1==0): cols -> gates i, f ; odd lane: gates g, o
    {
        const int par = l & 1;
        // preload kp/bp for this thread's 8 columns
        float kpv[4][2], bpv[4][2];
        #pragma unroll
        for (int jn = 0; jn < 4; jn++) {
            #pragma unroll
            for (int q = 0; q < 2; q++) {
                int n = n0 + n_off + jn * 8 + (l & 3) * 2 + q;
                kpv[jn][q] = g_kp[n];
                bpv[jn][q] = g_bp[n];
            }
        }
        #pragma unroll
        for (int im = 0; im < 2; im++) {
            #pragma unroll
            for (int half = 0; half < 2; half++) {
                int row = m0 + m_off + im * 16 + (l >> 2) + half * 8;
                float xr = g_x[row];
                #pragma unroll
                for (int jn = 0; jn < 4; jn++) {
                    float zA = acc[im][jn][half * 2 + 0] + xr * kpv[jn][0] + bpv[jn][0];
                    float zB = acc[im][jn][half * 2 + 1] + xr * kpv[jn][1] + bpv[jn][1];
                    // even: iv = sig(zA), fv = sig(zB); odd: gv = tanh(zA), ov = sig(zB)
                    float vA = par ? tanhf_(zA) : sigf(zA);
                    float vB = sigf(zB);
                    int u = u0 + ((n_off + jn * 8 + (l & 3) * 2) >> 2);
                    size_t gi = (size_t)row * 1024 + u;
                    float gx = __shfl_xor_sync(0xFFFFFFFFu, vA, 1);  // even receives gv
                    float cn = 0.0f;
                    if (!par) {
                        float co = g_c[gi];
                        cn = vB * co + vA * gx;    // f*c + i*g
                        g_c[gi] = cn;
                    }
                    float cnx = __shfl_xor_sync(0xFFFFFFFFu, cn, 1); // odd receives cn
                    if (par) {
                        float hn = vB * tanhf_(cnx);   // o * tanh(c_new)
                        __nv_bfloat16 hi = __float2bfloat16(hn);
                        float lo = hn - __bfloat162float(hi);
                        g_hh[dst][gi] = hi;
                        g_hl[dst][gi] = __float2bfloat16(lo);
                    }
                }
            }
        }
    }
}

// ---------------- host side ----------------
extern "C" void kernel_launch(void* const* d_in, const int* in_sizes, int n_in,
                              void* d_out, int out_size) {
    const float* features = (const float*)d_in[0];
    const float* kern     = (const float*)d_in[1];
    const float* W        = (const float*)d_in[2];
    const float* bias     = (const float*)d_in[3];
    const float* dw       = (const float*)d_in[4];
    const float* db       = (const float*)d_in[5];
    float* out = (float*)d_out;

    cudaFuncSetAttribute(step_kernel, cudaFuncAttributeMaxDynamicSharedMemorySize, SMEM_DYN);

    prep_w_kernel<<<dim3(32, 128, 4), dim3(32, 8)>>>(W);
    prep_small_kernel<<<16, 256>>>(kern, bias);
    init_hc_kernel<<<4096, 1024>>>(features);

    for (int t = 0; t < TSTEPS; t++) {
        int src = t & 1;
        int dst = src ^ 1;
        step_kernel<<<2048, 256, SMEM_DYN>>>(src);
        collect_kernel<<<512, 256>>>(dw, db, out, dst, t);
    }
}

// round 9
// speedup vs baseline: 1.2929x; 1.2929x over previous
#include <cuda_runtime.h>
#include <cuda.h>
#include <cuda_bf16.h>
#include <cstdint>
#include <cstddef>

// ---------------- problem constants ----------------
#define BATCH   4096
#define UNITS   1024
#define TSTEPS  128
#define BM      128            // batch rows per tile
#define BN      128            // z-cols per tile = 32 units * 4 gates
#define KC      32             // K elements per chunk (64B rows, SW64)
#define NKC     32             // chunks over K=1024
#define ROWB    64             // smem row bytes (swizzled, no pad)
#define PL      (128 * ROWB)   // 8192 B per plane
#define O_AH    0
#define O_AL    (PL)
#define O_BH    (2 * PL)
#define O_BL    (3 * PL)
#define STAGE   (4 * PL)       // 32768 B
#define NSTG    3
#define SMEM_DYN (NSTG * STAGE)   // 98304 B (2 CTAs/SM fit)
#define HN      (4096UL * 1024UL)

// ---------------- device-global state ----------------
__device__ __nv_bfloat16 g_hh[2][HN];   // hidden hi (ping/pong)  [4096][1024]
__device__ __nv_bfloat16 g_hl[2][HN];   // hidden lo
__device__ __nv_bfloat16 g_Wh[HN * 4];  // permuted W hi: [n=4u+g][k]  (4096x1024)
__device__ __nv_bfloat16 g_Wl[HN * 4];  // permuted W lo
__device__ float         g_c[HN];       // cell state fp32, in place
__device__ float         g_kp[4 * UNITS];   // permuted input kernel
__device__ float         g_bp[4 * UNITS];   // permuted bias
__device__ float         g_x[BATCH];        // autoregressive feedback input

// ---------------- PTX helpers ----------------
__device__ __forceinline__ uint32_t smem_u32(const void* p) {
    uint32_t a;
    asm("{ .reg .u64 t; cvta.to.shared.u64 t, %1; cvt.u32.u64 %0, t; }" : "=r"(a) : "l"(p));
    return a;
}
__device__ __forceinline__ void mbar_init(uint32_t a, uint32_t c) {
    asm volatile("mbarrier.init.shared.b64 [%0], %1;" :: "r"(a), "r"(c) : "memory");
}
__device__ __forceinline__ void mbar_expect(uint32_t a, uint32_t bytes) {
    asm volatile("mbarrier.arrive.expect_tx.shared.b64 _, [%0], %1;" :: "r"(a), "r"(bytes) : "memory");
}
__device__ __forceinline__ void mbar_wait(uint32_t a, uint32_t ph) {
    asm volatile(
        "{\n\t.reg .pred P;\n"
        "WL%=:\n\t"
        "mbarrier.try_wait.parity.acquire.cta.shared::cta.b64 P, [%0], %1, 0x989680;\n\t"
        "@P bra.uni WD%=;\n\t"
        "bra.uni WL%=;\n"
        "WD%=:\n\t}"
        :: "r"(a), "r"(ph) : "memory");
}
__device__ __forceinline__ void tma3d(uint32_t dst, const CUtensorMap* m, int x, int y, int z, uint32_t bar) {
    asm volatile(
        "cp.async.bulk.tensor.3d.shared::cta.global.tile.mbarrier::complete_tx::bytes "
        "[%0], [%1, {%2, %3, %4}], [%5];"
        :: "r"(dst), "l"(m), "r"(x), "r"(y), "r"(z), "r"(bar) : "memory");
}
__device__ __forceinline__ void tma2d(uint32_t dst, const CUtensorMap* m, int x, int y, uint32_t bar) {
    asm volatile(
        "cp.async.bulk.tensor.2d.shared::cta.global.tile.mbarrier::complete_tx::bytes "
        "[%0], [%1, {%2, %3}], [%4];"
        :: "r"(dst), "l"(m), "r"(x), "r"(y), "r"(bar) : "memory");
}
__device__ __forceinline__ void ldsm_x4(uint32_t addr, uint32_t* r) {
    asm volatile("ldmatrix.sync.aligned.m8n8.x4.shared.b16 {%0,%1,%2,%3}, [%4];"
                 : "=r"(r[0]), "=r"(r[1]), "=r"(r[2]), "=r"(r[3]) : "r"(addr));
}
__device__ __forceinline__ void mma_bf16(float* d, const uint32_t* a, const uint32_t* b) {
    asm volatile(
        "mma.sync.aligned.m16n8k16.row.col.f32.bf16.bf16.f32 "
        "{%0,%1,%2,%3}, {%4,%5,%6,%7}, {%8,%9}, {%0,%1,%2,%3};"
        : "+f"(d[0]), "+f"(d[1]), "+f"(d[2]), "+f"(d[3])
        : "r"(a[0]), "r"(a[1]), "r"(a[2]), "r"(a[3]), "r"(b[0]), "r"(b[1]));
}
__device__ __forceinline__ float sigf(float x) {
    return __fdividef(1.0f, 1.0f + __expf(-x));
}
__device__ __forceinline__ float tanhf_(float x) {
    return __fdividef(2.0f, 1.0f + __expf(-2.0f * x)) - 1.0f;
}
__device__ __forceinline__ uint32_t swz64(uint32_t off) {
    return off ^ ((off >> 3) & 0x30);
}

// ---------------- prep kernels ----------------
__global__ void prep_w_kernel(const float* __restrict__ W) {
    int u = blockIdx.x * 32 + threadIdx.x;
    int k = blockIdx.y * 8 + threadIdx.y;
    int g = blockIdx.z;
    float v = W[(size_t)k * 4096 + g * 1024 + u];
    __nv_bfloat16 hi = __float2bfloat16(v);
    float lo = v - __bfloat162float(hi);
    size_t o = ((size_t)(4 * u + g)) * 1024 + k;
    g_Wh[o] = hi;
    g_Wl[o] = __float2bfloat16(lo);
}

__global__ void prep_small_kernel(const float* __restrict__ kern, const float* __restrict__ bias) {
    int idx = blockIdx.x * 256 + threadIdx.x;   // 0..4095
    int g = idx & 3, u = idx >> 2;
    int c = g * 1024 + u;
    g_kp[idx] = kern[c];
    g_bp[idx] = bias[c];
    g_x[idx] = 0.0f;
}

__global__ void init_hc_kernel(const float* __restrict__ feat) {
    size_t idx = (size_t)blockIdx.x * 1024 + threadIdx.x;
    int b = blockIdx.x, u = threadIdx.x;
    float v = feat[(size_t)b * 512 + (u & 511)];
    __nv_bfloat16 hi = __float2bfloat16(v);
    float lo = v - __bfloat162float(hi);
    g_hh[0][idx] = hi;
    g_hl[0][idx] = __float2bfloat16(lo);
    g_c[idx] = v;
}

// pred[b] = (h_hi+h_lo)[b,:] . dw + db ; write out[b][t], feedback g_x[b]
__global__ void collect_kernel(const float* __restrict__ dw, const float* __restrict__ db,
                               float* __restrict__ out, int dst, int t) {
    int wid = threadIdx.x >> 5, lid = threadIdx.x & 31;
    int row = blockIdx.x * 8 + wid;
    const __nv_bfloat16* hh = g_hh[dst];
    const __nv_bfloat16* hl = g_hl[dst];
    size_t base = (size_t)row * 1024;
    float s = 0.0f;
    #pragma unroll
    for (int i = 0; i < 32; i++) {
        int u = i * 32 + lid;
        float h = __bfloat162float(hh[base + u]) + __bfloat162float(hl[base + u]);
        s += h * dw[u];
    }
    #pragma unroll
    for (int o = 16; o; o >>= 1) s += __shfl_down_sync(0xFFFFFFFFu, s, o);
    if (lid == 0) {
        float p = s + db[0];
        out[(size_t)row * TSTEPS + t] = p;
        g_x[row] = p;
    }
}

// ---------------- fused LSTM step (bf16 3-pass, TMA producer) ----------------
__global__ void __launch_bounds__(256, 2)
step_kernel(const __grid_constant__ CUtensorMap mAh,
            const __grid_constant__ CUtensorMap mAl,
            const __grid_constant__ CUtensorMap mBh,
            const __grid_constant__ CUtensorMap mBl,
            int src)
{
    extern __shared__ __align__(1024) char sm[];
    __shared__ uint64_t barmem[NSTG];

    const int tid = threadIdx.x;
    const int w = tid >> 5, l = tid & 31;
    const int dst = src ^ 1;
    const int mt = blockIdx.x & 31, nt = blockIdx.x >> 5;
    const int m0 = mt << 7;      // batch row base
    const int n0 = nt << 7;      // z col base (128 cols)
    const int u0 = nt << 5;      // unit base (32 units)

    const uint32_t sb = smem_u32(sm);
    uint32_t bars[NSTG];
    #pragma unroll
    for (int s = 0; s < NSTG; s++) bars[s] = smem_u32(&barmem[s]);

    if (tid == 0) {
        #pragma unroll
        for (int s = 0; s < NSTG; s++) mbar_init(bars[s], 1);
        asm volatile("fence.proxy.async.shared::cta;" ::: "memory");
    }
    __syncthreads();

    // producer: issue chunk kc into stage kc%3 (tid 0 only)
    auto issue = [&](int kc) {
        int s = kc % NSTG;
        uint32_t st = sb + (uint32_t)s * STAGE;
        int k0 = kc * KC;
        mbar_expect(bars[s], STAGE);
        tma3d(st + O_AH, &mAh, k0, m0, src, bars[s]);
        tma3d(st + O_AL, &mAl, k0, m0, src, bars[s]);
        tma2d(st + O_BH, &mBh, k0, n0, bars[s]);
        tma2d(st + O_BL, &mBl, k0, n0, bars[s]);
    };
    if (tid == 0) { issue(0); issue(1); issue(2); }

    // warp tiling: 4 (m) x 2 (n); warp tile 32x64
    const int m_off = (w & 3) * 32;
    const int n_off = (w >> 2) * 64;

    float acc[2][8][4];
    #pragma unroll
    for (int im = 0; im < 2; im++)
        #pragma unroll
        for (int jn = 0; jn < 8; jn++)
            #pragma unroll
            for (int q = 0; q < 4; q++) acc[im][jn][q] = 0.0f;

    // ldsm address helpers (SW64-swizzled 64B rows)
    auto a_addr = [&](uint32_t plane, int im, int ks) -> uint32_t {
        int row = m_off + im * 16 + (l & 15);
        uint32_t off = (uint32_t)row * ROWB + ks * 32 + ((l >> 4) << 4);
        return plane + swz64(off);
    };
    auto b_addr = [&](uint32_t plane, int jn2, int ks) -> uint32_t {
        int row = n_off + jn2 * 16 + (l & 7) + ((l >> 4) << 3);
        uint32_t off = (uint32_t)row * ROWB + ks * 32 + (((l >> 3) & 1) << 4);
        return plane + swz64(off);
    };

    // -------- mainloop: 3-stage TMA pipeline, one sync per chunk --------
    for (int kc = 0; kc < NKC; kc++) {
        const int s = kc % NSTG;
        const uint32_t so = sb + (uint32_t)s * STAGE;
        mbar_wait(bars[s], (kc / NSTG) & 1);
        #pragma unroll
        for (int ks = 0; ks < 2; ks++) {
            uint32_t ah[2][4], al[2][4], bb[16];
            #pragma unroll
            for (int im = 0; im < 2; im++) ldsm_x4(a_addr(so + O_AH, im, ks), ah[im]);
            #pragma unroll
            for (int im = 0; im < 2; im++) ldsm_x4(a_addr(so + O_AL, im, ks), al[im]);
            #pragma unroll
            for (int jn2 = 0; jn2 < 4; jn2++) ldsm_x4(b_addr(so + O_BH, jn2, ks), &bb[jn2 * 4]);
            // hi*hi and lo*hi against resident B_hi
            #pragma unroll
            for (int im = 0; im < 2; im++)
                #pragma unroll
                for (int jn = 0; jn < 8; jn++)
                    mma_bf16(acc[im][jn], ah[im], &bb[(jn >> 1) * 4 + (jn & 1) * 2]);
            #pragma unroll
            for (int im = 0; im < 2; im++)
                #pragma unroll
                for (int jn = 0; jn < 8; jn++)
                    mma_bf16(acc[im][jn], al[im], &bb[(jn >> 1) * 4 + (jn & 1) * 2]);
            // overwrite with B_lo, hi*lo
            #pragma unroll
            for (int jn2 = 0; jn2 < 4; jn2++) ldsm_x4(b_addr(so + O_BL, jn2, ks), &bb[jn2 * 4]);
            #pragma unroll
            for (int im = 0; im < 2; im++)
                #pragma unroll
                for (int jn = 0; jn < 8; jn++)
                    mma_bf16(acc[im][jn], ah[im], &bb[(jn >> 1) * 4 + (jn & 1) * 2]);
        }
        __syncthreads();                       // all reads of stage s complete
        if (tid == 0 && kc + NSTG < NKC) issue(kc + NSTG);
    }

    // -------- fragment-direct epilogue (no smem, shfl-paired gates) --------
    // lane pair (l, l^1) owns the 4 gates of one (row, unit):
    //   even lane: gates i, f ; odd lane: gates g, o
    {
        const int par = l & 1;
        float kpv[8][2], bpv[8][2];
        #pragma unroll
        for (int jn = 0; jn < 8; jn++) {
            #pragma unroll
            for (int q = 0; q < 2; q++) {
                int n = n0 + n_off + jn * 8 + (l & 3) * 2 + q;
                kpv[jn][q] = g_kp[n];
                bpv[jn][q] = g_bp[n];
            }
        }
        #pragma unroll
        for (int im = 0; im < 2; im++) {
            #pragma unroll
            for (int half = 0; half < 2; half++) {
                int row = m0 + m_off + im * 16 + (l >> 2) + half * 8;
                float xr = g_x[row];
                #pragma unroll
                for (int jn = 0; jn < 8; jn++) {
                    float zA = acc[im][jn][half * 2 + 0] + xr * kpv[jn][0] + bpv[jn][0];
                    float zB = acc[im][jn][half * 2 + 1] + xr * kpv[jn][1] + bpv[jn][1];
                    float vA = par ? tanhf_(zA) : sigf(zA);
                    float vB = sigf(zB);
                    int u = u0 + ((n_off + jn * 8 + (l & 3) * 2) >> 2);
                    size_t gi = (size_t)row * 1024 + u;
                    float gx = __shfl_xor_sync(0xFFFFFFFFu, vA, 1);  // even receives gv
                    float cn = 0.0f;
                    if (!par) {
                        float co = g_c[gi];
                        cn = vB * co + vA * gx;    // f*c + i*g
                        g_c[gi] = cn;
                    }
                    float cnx = __shfl_xor_sync(0xFFFFFFFFu, cn, 1); // odd receives cn
                    if (par) {
                        float hn = vB * tanhf_(cnx);   // o * tanh(c_new)
                        __nv_bfloat16 hi = __float2bfloat16(hn);
                        float lo = hn - __bfloat162float(hi);
                        g_hh[dst][gi] = hi;
                        g_hl[dst][gi] = __float2bfloat16(lo);
                    }
                }
            }
        }
    }
}

// ---------------- host side ----------------
typedef CUresult (*PFN_tmap)(CUtensorMap*, CUtensorMapDataType, cuuint32_t, void*,
    const cuuint64_t*, const cuuint64_t*, const cuuint32_t*, const cuuint32_t*,
    CUtensorMapInterleave, CUtensorMapSwizzle, CUtensorMapL2promotion, CUtensorMapFloatOOBfill);

static void enc2d(PFN_tmap fn, CUtensorMap* m, void* base) {
    cuuint64_t dims[2]    = { 1024, 4096 };
    cuuint64_t strides[1] = { 2048 };
    cuuint32_t box[2]     = { KC, 128 };
    cuuint32_t es[2]      = { 1, 1 };
    fn(m, CU_TENSOR_MAP_DATA_TYPE_BFLOAT16, 2, base, dims, strides, box, es,
       CU_TENSOR_MAP_INTERLEAVE_NONE, CU_TENSOR_MAP_SWIZZLE_64B,
       CU_TENSOR_MAP_L2_PROMOTION_L2_128B, CU_TENSOR_MAP_FLOAT_OOB_FILL_NONE);
}
static void enc3d(PFN_tmap fn, CUtensorMap* m, void* base) {
    cuuint64_t dims[3]    = { 1024, 4096, 2 };
    cuuint64_t strides[2] = { 2048, 4096ULL * 2048ULL };
    cuuint32_t box[3]     = { KC, 128, 1 };
    cuuint32_t es[3]      = { 1, 1, 1 };
    fn(m, CU_TENSOR_MAP_DATA_TYPE_BFLOAT16, 3, base, dims, strides, box, es,
       CU_TENSOR_MAP_INTERLEAVE_NONE, CU_TENSOR_MAP_SWIZZLE_64B,
       CU_TENSOR_MAP_L2_PROMOTION_L2_128B, CU_TENSOR_MAP_FLOAT_OOB_FILL_NONE);
}

extern "C" void kernel_launch(void* const* d_in, const int* in_sizes, int n_in,
                              void* d_out, int out_size) {
    const float* features = (const float*)d_in[0];
    const float* kern     = (const float*)d_in[1];
    const float* W        = (const float*)d_in[2];
    const float* bias     = (const float*)d_in[3];
    const float* dw       = (const float*)d_in[4];
    const float* db       = (const float*)d_in[5];
    float* out = (float*)d_out;

    PFN_tmap enc = nullptr;
    {
        cudaDriverEntryPointQueryResult qr;
        void* fp = nullptr;
        cudaGetDriverEntryPointByVersion("cuTensorMapEncodeTiled", &fp, 12000,
                                         cudaEnableDefault, &qr);
        enc = (PFN_tmap)fp;
    }

    void *pHh = nullptr, *pHl = nullptr, *pWh = nullptr, *pWl = nullptr;
    cudaGetSymbolAddress(&pHh, g_hh);
    cudaGetSymbolAddress(&pHl, g_hl);
    cudaGetSymbolAddress(&pWh, g_Wh);
    cudaGetSymbolAddress(&pWl, g_Wl);

    CUtensorMap mAh, mAl, mBh, mBl;
    enc3d(enc, &mAh, pHh);
    enc3d(enc, &mAl, pHl);
    enc2d(enc, &mBh, pWh);
    enc2d(enc, &mBl, pWl);

    cudaFuncSetAttribute(step_kernel, cudaFuncAttributeMaxDynamicSharedMemorySize, SMEM_DYN);

    prep_w_kernel<<<dim3(32, 128, 4), dim3(32, 8)>>>(W);
    prep_small_kernel<<<16, 256>>>(kern, bias);
    init_hc_kernel<<<4096, 1024>>>(features);

    for (int t = 0; t < TSTEPS; t++) {
        int src = t & 1;
        int dst = src ^ 1;
        step_kernel<<<1024, 256, SMEM_DYN>>>(mAh, mAl, mBh, mBl, src);
        collect_kernel<<<512, 256>>>(dw, db, out, dst, t);
    }
}